// round 1
// baseline (speedup 1.0000x reference)
#include <cuda_runtime.h>
#include <math.h>

#define T_TOK 32768   // N*L tokens
#define H_DIM 768
#define C_CH  3
#define KFD   256
#define M_MLP 3072
#define LN_EPS 1e-6f

// Scratch (device globals; no allocations anywhere).
// s1: qkv [T,3,768] then MLP activations [T,3072]
// s2: h (LN1 out), then ctx [T*3,256], then y (LN2 out)
// xr: residual stream after attention
__device__ float g_s1[(size_t)T_TOK * M_MLP];
__device__ float g_s2[(size_t)T_TOK * H_DIM];
__device__ float g_xr[(size_t)T_TOK * H_DIM];

// ---------------------------------------------------------------- LayerNorm
__global__ void ln_kernel(const float* __restrict__ in,
                          const float* __restrict__ gam,
                          const float* __restrict__ bet,
                          float* __restrict__ out)
{
    int gwarp = (blockIdx.x * blockDim.x + threadIdx.x) >> 5;
    int lane  = threadIdx.x & 31;
    if (gwarp >= T_TOK) return;
    const float* row = in + (size_t)gwarp * H_DIM;
    float v[24];
    float s = 0.f, sq = 0.f;
#pragma unroll
    for (int i = 0; i < 24; i++) {
        v[i] = row[lane + 32 * i];
        s += v[i];
        sq += v[i] * v[i];
    }
#pragma unroll
    for (int o = 16; o > 0; o >>= 1) {
        s  += __shfl_xor_sync(0xffffffffu, s,  o);
        sq += __shfl_xor_sync(0xffffffffu, sq, o);
    }
    float mu  = s * (1.0f / H_DIM);
    float var = fmaxf(sq * (1.0f / H_DIM) - mu * mu, 0.0f);
    float rs  = rsqrtf(var + LN_EPS);
    float* orow = out + (size_t)gwarp * H_DIM;
#pragma unroll
    for (int i = 0; i < 24; i++) {
        int j = lane + 32 * i;
        orow[j] = (v[i] - mu) * rs * gam[j] + bet[j];
    }
}

// ------------------------------------------------- criss-cross attention core
// qkv layout: [T, C=3, 768] where per channel: [q(256) | k(256) | v(256)]
// ctx layout: [T*3, 256]  (row = t*3 + d_channel)
__global__ void attn_kernel(const float* __restrict__ qkv, float* __restrict__ ctx)
{
    int gid = blockIdx.x * blockDim.x + threadIdx.x; // t*256 + kf
    int t  = gid >> 8;
    int kf = gid & 255;
    const float* base = qkv + (size_t)t * (3 * H_DIM);
    float q[3], k[3], v[3];
#pragma unroll
    for (int c = 0; c < 3; c++) {
        q[c] = base[c * H_DIM + kf];
        k[c] = base[c * H_DIM + KFD + kf];
        v[c] = base[c * H_DIM + 2 * KFD + kf];
    }
    const float scale = 0.0625f; // 1/sqrt(256)
    float o0 = 0.f, o1 = 0.f, o2 = 0.f;
#pragma unroll
    for (int c = 0; c < 3; c++) {
        float s0 = q[c] * k[0] * scale;
        float s1 = q[c] * k[1] * scale;
        float s2 = q[c] * k[2] * scale;
        float m  = fmaxf(s0, fmaxf(s1, s2));
        float e0 = __expf(s0 - m), e1 = __expf(s1 - m), e2 = __expf(s2 - m);
        float inv = v[c] / (e0 + e1 + e2);
        o0 = fmaf(e0, inv, o0);
        o1 = fmaf(e1, inv, o1);
        o2 = fmaf(e2, inv, o2);
    }
    size_t ob = (size_t)t * 3 * KFD + kf;
    ctx[ob]           = o0;
    ctx[ob + KFD]     = o1;
    ctx[ob + 2 * KFD] = o2;
}

// ---------------------------------------------------------------- SGEMM
// C[M,N] = A[M,K] @ B[K,N] + bias[N]  (+ res, or GELU), all row-major, strided.
// BM=BN=128, BK=8, 256 threads, 8x8 per-thread tile (2x2 quads of 4x4).
// All problem dims are multiples of tiles -> no bounds checks.
__device__ __forceinline__ float gelu_exact(float x)
{
    return 0.5f * x * (1.0f + erff(x * 0.70710678118654752f));
}

template <int EPI>  // 0: +bias, 1: +bias+res, 2: gelu(+bias)
__global__ void __launch_bounds__(256, 2)
sgemm_kernel(int K,
             const float* __restrict__ A, int lda,
             const float* __restrict__ B, int ldb,
             float* __restrict__ C, int ldc,
             const float* __restrict__ bias,
             const float* __restrict__ res)
{
    __shared__ float As[8][132];   // padded: conflict-free transposed stores
    __shared__ float Bs[8][128];

    const int tid = threadIdx.x;
    const int tx  = tid & 15;      // 0..15  -> column quads
    const int ty  = tid >> 4;      // 0..15  -> row quads
    const int row0 = blockIdx.y * 128;
    const int col0 = blockIdx.x * 128;

    const int arow  = tid >> 1;           // 0..127
    const int akcol = (tid & 1) * 4;      // 0 or 4
    const float* Aptr = A + (size_t)(row0 + arow) * lda + akcol;

    const int brow = tid >> 5;            // 0..7
    const int bcol = (tid & 31) * 4;      // 0..124
    const float* Bptr = B + (size_t)brow * ldb + col0 + bcol;

    float acc[8][8];
#pragma unroll
    for (int i = 0; i < 8; i++)
#pragma unroll
        for (int j = 0; j < 8; j++) acc[i][j] = 0.f;

    for (int k0 = 0; k0 < K; k0 += 8) {
        float4 av = *(const float4*)(Aptr + k0);
        float4 bv = *(const float4*)(Bptr + (size_t)k0 * ldb);
        As[akcol + 0][arow] = av.x;
        As[akcol + 1][arow] = av.y;
        As[akcol + 2][arow] = av.z;
        As[akcol + 3][arow] = av.w;
        *(float4*)&Bs[brow][bcol] = bv;
        __syncthreads();
#pragma unroll
        for (int k = 0; k < 8; k++) {
            float4 a0 = *(const float4*)&As[k][ty * 4];
            float4 a1 = *(const float4*)&As[k][64 + ty * 4];
            float4 b0 = *(const float4*)&Bs[k][tx * 4];
            float4 b1 = *(const float4*)&Bs[k][64 + tx * 4];
            float a[8] = {a0.x, a0.y, a0.z, a0.w, a1.x, a1.y, a1.z, a1.w};
            float b[8] = {b0.x, b0.y, b0.z, b0.w, b1.x, b1.y, b1.z, b1.w};
#pragma unroll
            for (int i = 0; i < 8; i++)
#pragma unroll
                for (int j = 0; j < 8; j++)
                    acc[i][j] = fmaf(a[i], b[j], acc[i][j]);
        }
        __syncthreads();
    }

#pragma unroll
    for (int i = 0; i < 8; i++) {
        int r = row0 + ((i < 4) ? (ty * 4 + i) : (64 + ty * 4 + i - 4));
#pragma unroll
        for (int jh = 0; jh < 2; jh++) {
            int c = col0 + jh * 64 + tx * 4;
            float4 bv = *(const float4*)(bias + c);
            float4 o;
            float* op = (float*)&o;
            const float* bp = (const float*)&bv;
            if (EPI == 1) {
                float4 rv = *(const float4*)(res + (size_t)r * ldc + c);
                const float* rp = (const float*)&rv;
#pragma unroll
                for (int j = 0; j < 4; j++)
                    op[j] = acc[i][jh * 4 + j] + bp[j] + rp[j];
            } else if (EPI == 2) {
#pragma unroll
                for (int j = 0; j < 4; j++)
                    op[j] = gelu_exact(acc[i][jh * 4 + j] + bp[j]);
            } else {
#pragma unroll
                for (int j = 0; j < 4; j++)
                    op[j] = acc[i][jh * 4 + j] + bp[j];
            }
            *(float4*)(C + (size_t)r * ldc + c) = o;
        }
    }
}

// ---------------------------------------------------------------- launch
extern "C" void kernel_launch(void* const* d_in, const int* in_sizes, int n_in,
                              void* d_out, int out_size)
{
    const float* x     = (const float*)d_in[0];
    const float* W_qkv = (const float*)d_in[1];
    const float* b_qkv = (const float*)d_in[2];
    const float* W_out = (const float*)d_in[3];
    const float* b_out = (const float*)d_in[4];
    const float* ln1_g = (const float*)d_in[5];
    const float* ln1_b = (const float*)d_in[6];
    const float* ln2_g = (const float*)d_in[7];
    const float* ln2_b = (const float*)d_in[8];
    const float* W1    = (const float*)d_in[9];
    const float* b1    = (const float*)d_in[10];
    const float* W2    = (const float*)d_in[11];
    const float* b2    = (const float*)d_in[12];
    float* out = (float*)d_out;

    float *s1, *s2, *xr;
    cudaGetSymbolAddress((void**)&s1, g_s1);
    cudaGetSymbolAddress((void**)&s2, g_s2);
    cudaGetSymbolAddress((void**)&xr, g_xr);

    // 1) LN1: x -> h (s2)
    ln_kernel<<<T_TOK / 8, 256>>>(x, ln1_g, ln1_b, s2);

    // 2) QKV per channel: h[:,c*256:+256] @ W_qkv[c] + b_qkv[c] -> s1[T,3,768]
    for (int c = 0; c < 3; c++) {
        sgemm_kernel<0><<<dim3(H_DIM / 128, T_TOK / 128), 256>>>(
            KFD,
            s2 + c * KFD, H_DIM,
            W_qkv + (size_t)c * KFD * 3 * KFD, 3 * KFD,
            s1 + c * 3 * KFD, C_CH * 3 * KFD,
            b_qkv + c * 3 * KFD, nullptr);
    }

    // 3) criss-cross attention: qkv(s1) -> ctx(s2) [T*3, 256]
    attn_kernel<<<(T_TOK * KFD) / 256, 256>>>(s1, s2);

    // 4) out-proj + residual: ctx @ W_out + b_out + x -> xr  (rows = T*3)
    sgemm_kernel<1><<<dim3(KFD / 128, (T_TOK * C_CH) / 128), 256>>>(
        KFD, s2, KFD, W_out, KFD, xr, KFD, b_out, x);

    // 5) LN2: xr -> y (s2)
    ln_kernel<<<T_TOK / 8, 256>>>(xr, ln2_g, ln2_b, s2);

    // 6) MLP fc1 + exact GELU: y @ W1 + b1 -> act (s1) [T, 3072]
    sgemm_kernel<2><<<dim3(M_MLP / 128, T_TOK / 128), 256>>>(
        H_DIM, s2, H_DIM, W1, M_MLP, s1, M_MLP, b1, nullptr);

    // 7) MLP fc2 + residual: act @ W2 + b2 + xr -> out
    sgemm_kernel<1><<<dim3(H_DIM / 128, T_TOK / 128), 256>>>(
        M_MLP, s1, M_MLP, W2, H_DIM, out, H_DIM, b2, xr);
}

// round 2
// speedup vs baseline: 2.1193x; 2.1193x over previous
#include <cuda_runtime.h>
#include <math.h>

#define T_TOK 32768   // N*L tokens
#define H_DIM 768
#define C_CH  3
#define KFD   256
#define M_MLP 3072
#define LN_EPS 1e-6f

// Scratch (device globals; no allocations anywhere).
__device__ __align__(16) float g_s1[(size_t)T_TOK * M_MLP];
__device__ __align__(16) float g_s2[(size_t)T_TOK * H_DIM];
__device__ __align__(16) float g_xr[(size_t)T_TOK * H_DIM];

// ---------------------------------------------------------------- LayerNorm
__global__ void ln_kernel(const float* __restrict__ in,
                          const float* __restrict__ gam,
                          const float* __restrict__ bet,
                          float* __restrict__ out)
{
    int gwarp = (blockIdx.x * blockDim.x + threadIdx.x) >> 5;
    int lane  = threadIdx.x & 31;
    if (gwarp >= T_TOK) return;
    const float* row = in + (size_t)gwarp * H_DIM;
    float v[24];
    float s = 0.f, sq = 0.f;
#pragma unroll
    for (int i = 0; i < 24; i++) {
        v[i] = row[lane + 32 * i];
        s += v[i];
        sq += v[i] * v[i];
    }
#pragma unroll
    for (int o = 16; o > 0; o >>= 1) {
        s  += __shfl_xor_sync(0xffffffffu, s,  o);
        sq += __shfl_xor_sync(0xffffffffu, sq, o);
    }
    float mu  = s * (1.0f / H_DIM);
    float var = fmaxf(sq * (1.0f / H_DIM) - mu * mu, 0.0f);
    float rs  = rsqrtf(var + LN_EPS);
    float* orow = out + (size_t)gwarp * H_DIM;
#pragma unroll
    for (int i = 0; i < 24; i++) {
        int j = lane + 32 * i;
        orow[j] = (v[i] - mu) * rs * gam[j] + bet[j];
    }
}

// ------------------------------------------------- criss-cross attention core
__global__ void attn_kernel(const float* __restrict__ qkv, float* __restrict__ ctx)
{
    int gid = blockIdx.x * blockDim.x + threadIdx.x; // t*256 + kf
    int t  = gid >> 8;
    int kf = gid & 255;
    const float* base = qkv + (size_t)t * (3 * H_DIM);
    float q[3], k[3], v[3];
#pragma unroll
    for (int c = 0; c < 3; c++) {
        q[c] = base[c * H_DIM + kf];
        k[c] = base[c * H_DIM + KFD + kf];
        v[c] = base[c * H_DIM + 2 * KFD + kf];
    }
    const float scale = 0.0625f; // 1/sqrt(256)
    float o0 = 0.f, o1 = 0.f, o2 = 0.f;
#pragma unroll
    for (int c = 0; c < 3; c++) {
        float s0 = q[c] * k[0] * scale;
        float s1 = q[c] * k[1] * scale;
        float s2 = q[c] * k[2] * scale;
        float m  = fmaxf(s0, fmaxf(s1, s2));
        float e0 = __expf(s0 - m), e1 = __expf(s1 - m), e2 = __expf(s2 - m);
        float inv = v[c] / (e0 + e1 + e2);
        o0 = fmaf(e0, inv, o0);
        o1 = fmaf(e1, inv, o1);
        o2 = fmaf(e2, inv, o2);
    }
    size_t ob = (size_t)t * 3 * KFD + kf;
    ctx[ob]           = o0;
    ctx[ob + KFD]     = o1;
    ctx[ob + 2 * KFD] = o2;
}

// ---------------------------------------------------------------- TF32 GEMM
__device__ __forceinline__ float gelu_exact(float x)
{
    return 0.5f * x * (1.0f + erff(x * 0.70710678118654752f));
}

__device__ __forceinline__ unsigned to_tf32(float x)
{
    unsigned u;
    asm("cvt.rna.tf32.f32 %0, %1;" : "=r"(u) : "f"(x));
    return u;
}

__device__ __forceinline__ void mma_tf32(float* d, const unsigned* a, const unsigned* b)
{
    asm volatile(
        "mma.sync.aligned.m16n8k8.row.col.f32.tf32.tf32.f32 "
        "{%0,%1,%2,%3}, {%4,%5,%6,%7}, {%8,%9}, {%0,%1,%2,%3};\n"
        : "+f"(d[0]), "+f"(d[1]), "+f"(d[2]), "+f"(d[3])
        : "r"(a[0]), "r"(a[1]), "r"(a[2]), "r"(a[3]), "r"(b[0]), "r"(b[1]));
}

// C[M,N] = A[M,K] @ B[K,N] (+bias / +bias+res / gelu(+bias)), row-major.
// CTA tile 128x128, BK=16, 8 warps (2x4), warp tile 64x32.
// smem stride 136 words => fragment loads conflict-free: bank=(8k+col)%32.
template <int EPI>  // 0: +bias, 1: +bias+res, 2: gelu(+bias)
__global__ void __launch_bounds__(256)
tgemm_kernel(int K,
             const float* __restrict__ A, int lda,
             const float* __restrict__ B, int ldb,
             float* __restrict__ C, int ldc,
             const float* __restrict__ bias,
             const float* __restrict__ res)
{
    __shared__ unsigned As[16][136];   // [k][m]
    __shared__ unsigned Bs[16][136];   // [k][n]

    const int tid  = threadIdx.x;
    const int wid  = tid >> 5;
    const int lane = tid & 31;
    const int gID  = lane >> 2;   // 0..7
    const int tig  = lane & 3;    // 0..3
    const int wm   = (wid >> 2) * 64;   // warp row offset
    const int wn   = (wid & 3) * 32;    // warp col offset
    const int row0 = blockIdx.y * 128;
    const int col0 = blockIdx.x * 128;

    // global load mapping: A 128x16 (2 float4/thread), B 16x128 (2 float4/thread)
    const int arow = tid >> 1;
    const int ak   = (tid & 1) * 8;
    const float* Ag = A + (size_t)(row0 + arow) * lda + ak;
    const int brow = tid >> 4;
    const int bcol = (tid & 15) * 8;
    const float* Bg = B + (size_t)brow * ldb + col0 + bcol;

    float4 pa0 = *(const float4*)(Ag);
    float4 pa1 = *(const float4*)(Ag + 4);
    float4 pb0 = *(const float4*)(Bg);
    float4 pb1 = *(const float4*)(Bg + 4);

    float acc[4][4][4];
#pragma unroll
    for (int mi = 0; mi < 4; mi++)
#pragma unroll
        for (int ni = 0; ni < 4; ni++)
#pragma unroll
            for (int j = 0; j < 4; j++) acc[mi][ni][j] = 0.f;

    for (int k0 = 0; k0 < K; k0 += 16) {
        // stage current tile into smem (convert to tf32 once here)
        As[ak + 0][arow] = to_tf32(pa0.x);
        As[ak + 1][arow] = to_tf32(pa0.y);
        As[ak + 2][arow] = to_tf32(pa0.z);
        As[ak + 3][arow] = to_tf32(pa0.w);
        As[ak + 4][arow] = to_tf32(pa1.x);
        As[ak + 5][arow] = to_tf32(pa1.y);
        As[ak + 6][arow] = to_tf32(pa1.z);
        As[ak + 7][arow] = to_tf32(pa1.w);
        Bs[brow][bcol + 0] = to_tf32(pb0.x);
        Bs[brow][bcol + 1] = to_tf32(pb0.y);
        Bs[brow][bcol + 2] = to_tf32(pb0.z);
        Bs[brow][bcol + 3] = to_tf32(pb0.w);
        Bs[brow][bcol + 4] = to_tf32(pb1.x);
        Bs[brow][bcol + 5] = to_tf32(pb1.y);
        Bs[brow][bcol + 6] = to_tf32(pb1.z);
        Bs[brow][bcol + 7] = to_tf32(pb1.w);
        __syncthreads();

        // prefetch next tile (overlaps with compute below)
        if (k0 + 16 < K) {
            pa0 = *(const float4*)(Ag + k0 + 16);
            pa1 = *(const float4*)(Ag + k0 + 20);
            pb0 = *(const float4*)(Bg + (size_t)(k0 + 16) * ldb);
            pb1 = *(const float4*)(Bg + (size_t)(k0 + 16) * ldb + 4);
        }

#pragma unroll
        for (int ks = 0; ks < 16; ks += 8) {
            unsigned af[4][4], bf[4][2];
#pragma unroll
            for (int mi = 0; mi < 4; mi++) {
                int m = wm + mi * 16 + gID;
                af[mi][0] = As[ks + tig][m];
                af[mi][1] = As[ks + tig][m + 8];
                af[mi][2] = As[ks + tig + 4][m];
                af[mi][3] = As[ks + tig + 4][m + 8];
            }
#pragma unroll
            for (int ni = 0; ni < 4; ni++) {
                int n = wn + ni * 8 + gID;
                bf[ni][0] = Bs[ks + tig][n];
                bf[ni][1] = Bs[ks + tig + 4][n];
            }
#pragma unroll
            for (int mi = 0; mi < 4; mi++)
#pragma unroll
                for (int ni = 0; ni < 4; ni++)
                    mma_tf32(acc[mi][ni], af[mi], bf[ni]);
        }
        __syncthreads();
    }

    // epilogue: each (mi,ni,half) is a float2 at (r, c)
#pragma unroll
    for (int mi = 0; mi < 4; mi++) {
#pragma unroll
        for (int ni = 0; ni < 4; ni++) {
            int c = col0 + wn + ni * 8 + tig * 2;
            float2 bv = *(const float2*)(bias + c);
#pragma unroll
            for (int h = 0; h < 2; h++) {
                int r = row0 + wm + mi * 16 + gID + h * 8;
                float v0 = acc[mi][ni][h * 2 + 0] + bv.x;
                float v1 = acc[mi][ni][h * 2 + 1] + bv.y;
                if (EPI == 1) {
                    float2 rv = *(const float2*)(res + (size_t)r * ldc + c);
                    v0 += rv.x;
                    v1 += rv.y;
                } else if (EPI == 2) {
                    v0 = gelu_exact(v0);
                    v1 = gelu_exact(v1);
                }
                float2 o = make_float2(v0, v1);
                *(float2*)(C + (size_t)r * ldc + c) = o;
            }
        }
    }
}

// ---------------------------------------------------------------- launch
extern "C" void kernel_launch(void* const* d_in, const int* in_sizes, int n_in,
                              void* d_out, int out_size)
{
    const float* x     = (const float*)d_in[0];
    const float* W_qkv = (const float*)d_in[1];
    const float* b_qkv = (const float*)d_in[2];
    const float* W_out = (const float*)d_in[3];
    const float* b_out = (const float*)d_in[4];
    const float* ln1_g = (const float*)d_in[5];
    const float* ln1_b = (const float*)d_in[6];
    const float* ln2_g = (const float*)d_in[7];
    const float* ln2_b = (const float*)d_in[8];
    const float* W1    = (const float*)d_in[9];
    const float* b1    = (const float*)d_in[10];
    const float* W2    = (const float*)d_in[11];
    const float* b2    = (const float*)d_in[12];
    float* out = (float*)d_out;

    float *s1, *s2, *xr;
    cudaGetSymbolAddress((void**)&s1, g_s1);
    cudaGetSymbolAddress((void**)&s2, g_s2);
    cudaGetSymbolAddress((void**)&xr, g_xr);

    // 1) LN1: x -> h (s2)
    ln_kernel<<<T_TOK / 8, 256>>>(x, ln1_g, ln1_b, s2);

    // 2) QKV per channel: h[:,c*256:+256] @ W_qkv[c] + b_qkv[c] -> s1[T,3,768]
    for (int c = 0; c < 3; c++) {
        tgemm_kernel<0><<<dim3(H_DIM / 128, T_TOK / 128), 256>>>(
            KFD,
            s2 + c * KFD, H_DIM,
            W_qkv + (size_t)c * KFD * 3 * KFD, 3 * KFD,
            s1 + c * 3 * KFD, C_CH * 3 * KFD,
            b_qkv + c * 3 * KFD, nullptr);
    }

    // 3) criss-cross attention: qkv(s1) -> ctx(s2) [T*3, 256]
    attn_kernel<<<(T_TOK * KFD) / 256, 256>>>(s1, s2);

    // 4) out-proj + residual: ctx @ W_out + b_out + x -> xr  (rows = T*3)
    tgemm_kernel<1><<<dim3(KFD / 128, (T_TOK * C_CH) / 128), 256>>>(
        KFD, s2, KFD, W_out, KFD, xr, KFD, b_out, x);

    // 5) LN2: xr -> y (s2)
    ln_kernel<<<T_TOK / 8, 256>>>(xr, ln2_g, ln2_b, s2);

    // 6) MLP fc1 + exact GELU: y @ W1 + b1 -> act (s1) [T, 3072]
    tgemm_kernel<2><<<dim3(M_MLP / 128, T_TOK / 128), 256>>>(
        H_DIM, s2, H_DIM, W1, M_MLP, s1, M_MLP, b1, nullptr);

    // 7) MLP fc2 + residual: act @ W2 + b2 + xr -> out
    tgemm_kernel<1><<<dim3(H_DIM / 128, T_TOK / 128), 256>>>(
        M_MLP, s1, M_MLP, W2, H_DIM, out, H_DIM, b2, xr);
}

// round 3
// speedup vs baseline: 2.8171x; 1.3292x over previous
#include <cuda_runtime.h>
#include <math.h>

#define T_TOK 32768   // N*L tokens
#define H_DIM 768
#define C_CH  3
#define KFD   256
#define M_MLP 3072
#define LN_EPS 1e-6f

// GEMM tiling
#define BM 128
#define BN 256
#define BK 16
#define STAGES 3
#define A_STRIDE 20      // words per A row in smem (padded, conflict-free)
#define B_STRIDE 264     // words per B row in smem (padded, conflict-free)
#define A_STAGE_WORDS (BM * A_STRIDE)          // 2560
#define B_STAGE_WORDS (BK * B_STRIDE)          // 4224
#define SMEM_WORDS (STAGES * (A_STAGE_WORDS + B_STAGE_WORDS))
#define SMEM_BYTES (SMEM_WORDS * 4)            // 81408

// Scratch (device globals; no allocations anywhere).
__device__ __align__(16) float g_s1[(size_t)T_TOK * M_MLP];
__device__ __align__(16) float g_s2[(size_t)T_TOK * H_DIM];
__device__ __align__(16) float g_xr[(size_t)T_TOK * H_DIM];
// tf32-converted weights: W_qkv(589824) | W_out(65536) | W1(2359296) | W2(2359296)
#define WOFF_QKV 0
#define WOFF_OUT 589824
#define WOFF_W1  655360
#define WOFF_W2  3014656
__device__ __align__(16) float g_w[5373952];

// ---------------------------------------------------------------- helpers
__device__ __forceinline__ float ftf32(float x)
{
    unsigned u;
    asm("cvt.rna.tf32.f32 %0, %1;" : "=r"(u) : "f"(x));
    return __uint_as_float(u);
}

__device__ __forceinline__ float gelu_exact(float x)
{
    return 0.5f * x * (1.0f + erff(x * 0.70710678118654752f));
}

__device__ __forceinline__ void cp16(float* dst_smem, const float* src)
{
    unsigned d = (unsigned)__cvta_generic_to_shared(dst_smem);
    asm volatile("cp.async.cg.shared.global [%0], [%1], 16;\n" :: "r"(d), "l"(src));
}

__device__ __forceinline__ void mma_tf32(float* d, const unsigned* a, const unsigned* b)
{
    asm volatile(
        "mma.sync.aligned.m16n8k8.row.col.f32.tf32.tf32.f32 "
        "{%0,%1,%2,%3}, {%4,%5,%6,%7}, {%8,%9}, {%0,%1,%2,%3};\n"
        : "+f"(d[0]), "+f"(d[1]), "+f"(d[2]), "+f"(d[3])
        : "r"(a[0]), "r"(a[1]), "r"(a[2]), "r"(a[3]), "r"(b[0]), "r"(b[1]));
}

// ---------------------------------------------------------------- weight cvt
__global__ void cvt_kernel(const float* __restrict__ in, float* __restrict__ out, int n)
{
    int i = blockIdx.x * blockDim.x + threadIdx.x;
    if (i < n) out[i] = ftf32(in[i]);
}

// ---------------------------------------------------------------- LayerNorm
// Writes tf32-rounded output (consumed only by tensor-core GEMMs).
__global__ void ln_kernel(const float* __restrict__ in,
                          const float* __restrict__ gam,
                          const float* __restrict__ bet,
                          float* __restrict__ out)
{
    int gwarp = (blockIdx.x * blockDim.x + threadIdx.x) >> 5;
    int lane  = threadIdx.x & 31;
    if (gwarp >= T_TOK) return;
    const float* row = in + (size_t)gwarp * H_DIM;
    float v[24];
    float s = 0.f, sq = 0.f;
#pragma unroll
    for (int i = 0; i < 24; i++) {
        v[i] = row[lane + 32 * i];
        s += v[i];
        sq += v[i] * v[i];
    }
#pragma unroll
    for (int o = 16; o > 0; o >>= 1) {
        s  += __shfl_xor_sync(0xffffffffu, s,  o);
        sq += __shfl_xor_sync(0xffffffffu, sq, o);
    }
    float mu  = s * (1.0f / H_DIM);
    float var = fmaxf(sq * (1.0f / H_DIM) - mu * mu, 0.0f);
    float rs  = rsqrtf(var + LN_EPS);
    float* orow = out + (size_t)gwarp * H_DIM;
#pragma unroll
    for (int i = 0; i < 24; i++) {
        int j = lane + 32 * i;
        orow[j] = ftf32((v[i] - mu) * rs * gam[j] + bet[j]);
    }
}

// ------------------------------------------------- criss-cross attention core
// ctx written tf32-rounded (consumed only by out-proj GEMM).
__global__ void attn_kernel(const float* __restrict__ qkv, float* __restrict__ ctx)
{
    int gid = blockIdx.x * blockDim.x + threadIdx.x; // t*256 + kf
    int t  = gid >> 8;
    int kf = gid & 255;
    const float* base = qkv + (size_t)t * (3 * H_DIM);
    float q[3], k[3], v[3];
#pragma unroll
    for (int c = 0; c < 3; c++) {
        q[c] = base[c * H_DIM + kf];
        k[c] = base[c * H_DIM + KFD + kf];
        v[c] = base[c * H_DIM + 2 * KFD + kf];
    }
    const float scale = 0.0625f; // 1/sqrt(256)
    float o0 = 0.f, o1 = 0.f, o2 = 0.f;
#pragma unroll
    for (int c = 0; c < 3; c++) {
        float s0 = q[c] * k[0] * scale;
        float s1 = q[c] * k[1] * scale;
        float s2 = q[c] * k[2] * scale;
        float m  = fmaxf(s0, fmaxf(s1, s2));
        float e0 = __expf(s0 - m), e1 = __expf(s1 - m), e2 = __expf(s2 - m);
        float inv = v[c] / (e0 + e1 + e2);
        o0 = fmaf(e0, inv, o0);
        o1 = fmaf(e1, inv, o1);
        o2 = fmaf(e2, inv, o2);
    }
    size_t ob = (size_t)t * 3 * KFD + kf;
    ctx[ob]           = ftf32(o0);
    ctx[ob + KFD]     = ftf32(o1);
    ctx[ob + 2 * KFD] = ftf32(o2);
}

// ---------------------------------------------------------------- TF32 GEMM
// C[M,N] = A[M,K] @ B[K,N] (+bias / +bias+res / gelu(+bias)->tf32), row-major.
// CTA 128x256, BK=16, 3-stage cp.async pipeline, 8 warps (2x4), warp 64x64.
// A,B must already hold tf32-rounded fp32 bit patterns.
template <int EPI>  // 0: +bias, 1: +bias+res, 2: tf32(gelu(+bias))
__global__ void __launch_bounds__(256)
tgemm_kernel(int K,
             const float* __restrict__ A, int lda,
             const float* __restrict__ B, int ldb,
             float* __restrict__ C, int ldc,
             const float* __restrict__ bias,
             const float* __restrict__ res)
{
    extern __shared__ float smem[];
    float* As = smem;                                // STAGES * 2560 words
    float* Bs = smem + STAGES * A_STAGE_WORDS;       // STAGES * 4224 words

    const int tid  = threadIdx.x;
    const int wid  = tid >> 5;
    const int lane = tid & 31;
    const int gID  = lane >> 2;   // 0..7
    const int tig  = lane & 3;    // 0..3
    const int wm   = (wid >> 2) * 64;   // warp row offset (0/64)
    const int wn   = (wid & 3) * 64;    // warp col offset (0/64/128/192)
    const int row0 = blockIdx.y * BM;
    const int col0 = blockIdx.x * BN;

    const float* Ag = A + (size_t)row0 * lda;
    const float* Bg = B + col0;

    // copy mappings
    const int ar = tid >> 2;            // 0..63 (A rows ar and ar+64)
    const int ac = (tid & 3) * 4;       // k-chunk

    float acc[4][8][4];
#pragma unroll
    for (int mi = 0; mi < 4; mi++)
#pragma unroll
        for (int ni = 0; ni < 8; ni++)
#pragma unroll
            for (int j = 0; j < 4; j++) acc[mi][ni][j] = 0.f;

    const int nk = K / BK;

    // prologue: fill first STAGES-1 stages
#pragma unroll
    for (int s = 0; s < STAGES - 1; s++) {
        float* as = As + s * A_STAGE_WORDS;
        float* bs = Bs + s * B_STAGE_WORDS;
        int k0 = s * BK;
        cp16(as + ar * A_STRIDE + ac, Ag + (size_t)ar * lda + k0 + ac);
        cp16(as + (ar + 64) * A_STRIDE + ac, Ag + (size_t)(ar + 64) * lda + k0 + ac);
#pragma unroll
        for (int i = 0; i < 4; i++) {
            int ch = tid + 256 * i;
            int br = ch >> 6, bc = (ch & 63) * 4;
            cp16(bs + br * B_STRIDE + bc, Bg + (size_t)(k0 + br) * ldb + bc);
        }
        asm volatile("cp.async.commit_group;\n");
    }

    for (int kt = 0; kt < nk; kt++) {
        asm volatile("cp.async.wait_group %0;\n" :: "n"(STAGES - 2));
        __syncthreads();

        // issue copy for kt+STAGES-1 into buffer (kt+STAGES-1)%STAGES
        {
            int kf = kt + STAGES - 1;
            if (kf < nk) {
                int buf = kf % STAGES;
                float* as = As + buf * A_STAGE_WORDS;
                float* bs = Bs + buf * B_STAGE_WORDS;
                int k0 = kf * BK;
                cp16(as + ar * A_STRIDE + ac, Ag + (size_t)ar * lda + k0 + ac);
                cp16(as + (ar + 64) * A_STRIDE + ac, Ag + (size_t)(ar + 64) * lda + k0 + ac);
#pragma unroll
                for (int i = 0; i < 4; i++) {
                    int ch = tid + 256 * i;
                    int br = ch >> 6, bc = (ch & 63) * 4;
                    cp16(bs + br * B_STRIDE + bc, Bg + (size_t)(k0 + br) * ldb + bc);
                }
            }
            asm volatile("cp.async.commit_group;\n");
        }

        // compute on buffer kt%STAGES
        const float* as = As + (kt % STAGES) * A_STAGE_WORDS;
        const float* bs = Bs + (kt % STAGES) * B_STAGE_WORDS;
#pragma unroll
        for (int ks = 0; ks < BK; ks += 8) {
            unsigned af[4][4], bf[8][2];
#pragma unroll
            for (int mi = 0; mi < 4; mi++) {
                int m = wm + mi * 16 + gID;
                af[mi][0] = __float_as_uint(as[m * A_STRIDE + ks + tig]);
                af[mi][1] = __float_as_uint(as[(m + 8) * A_STRIDE + ks + tig]);
                af[mi][2] = __float_as_uint(as[m * A_STRIDE + ks + tig + 4]);
                af[mi][3] = __float_as_uint(as[(m + 8) * A_STRIDE + ks + tig + 4]);
            }
#pragma unroll
            for (int ni = 0; ni < 8; ni++) {
                int n = wn + ni * 8 + gID;
                bf[ni][0] = __float_as_uint(bs[(ks + tig) * B_STRIDE + n]);
                bf[ni][1] = __float_as_uint(bs[(ks + tig + 4) * B_STRIDE + n]);
            }
#pragma unroll
            for (int mi = 0; mi < 4; mi++)
#pragma unroll
                for (int ni = 0; ni < 8; ni++)
                    mma_tf32(acc[mi][ni], af[mi], bf[ni]);
        }
        __syncthreads();
    }

    // epilogue
#pragma unroll
    for (int mi = 0; mi < 4; mi++) {
#pragma unroll
        for (int ni = 0; ni < 8; ni++) {
            int c = col0 + wn + ni * 8 + tig * 2;
            float2 bv = *(const float2*)(bias + c);
#pragma unroll
            for (int h = 0; h < 2; h++) {
                int r = row0 + wm + mi * 16 + gID + h * 8;
                float v0 = acc[mi][ni][h * 2 + 0] + bv.x;
                float v1 = acc[mi][ni][h * 2 + 1] + bv.y;
                if (EPI == 1) {
                    float2 rv = *(const float2*)(res + (size_t)r * ldc + c);
                    v0 += rv.x;
                    v1 += rv.y;
                } else if (EPI == 2) {
                    v0 = ftf32(gelu_exact(v0));
                    v1 = ftf32(gelu_exact(v1));
                }
                *(float2*)(C + (size_t)r * ldc + c) = make_float2(v0, v1);
            }
        }
    }
}

// ---------------------------------------------------------------- launch
extern "C" void kernel_launch(void* const* d_in, const int* in_sizes, int n_in,
                              void* d_out, int out_size)
{
    const float* x     = (const float*)d_in[0];
    const float* W_qkv = (const float*)d_in[1];
    const float* b_qkv = (const float*)d_in[2];
    const float* W_out = (const float*)d_in[3];
    const float* b_out = (const float*)d_in[4];
    const float* ln1_g = (const float*)d_in[5];
    const float* ln1_b = (const float*)d_in[6];
    const float* ln2_g = (const float*)d_in[7];
    const float* ln2_b = (const float*)d_in[8];
    const float* W1    = (const float*)d_in[9];
    const float* b1    = (const float*)d_in[10];
    const float* W2    = (const float*)d_in[11];
    const float* b2    = (const float*)d_in[12];
    float* out = (float*)d_out;

    float *s1, *s2, *xr, *w;
    cudaGetSymbolAddress((void**)&s1, g_s1);
    cudaGetSymbolAddress((void**)&s2, g_s2);
    cudaGetSymbolAddress((void**)&xr, g_xr);
    cudaGetSymbolAddress((void**)&w,  g_w);

    static bool attr_done = false;
    if (!attr_done) {
        cudaFuncSetAttribute(tgemm_kernel<0>, cudaFuncAttributeMaxDynamicSharedMemorySize, SMEM_BYTES);
        cudaFuncSetAttribute(tgemm_kernel<1>, cudaFuncAttributeMaxDynamicSharedMemorySize, SMEM_BYTES);
        cudaFuncSetAttribute(tgemm_kernel<2>, cudaFuncAttributeMaxDynamicSharedMemorySize, SMEM_BYTES);
        attr_done = true;
    }

    // 0) tf32-round the weights
    cvt_kernel<<<(589824 + 255) / 256, 256>>>(W_qkv, w + WOFF_QKV, 589824);
    cvt_kernel<<<(65536 + 255) / 256, 256>>>(W_out, w + WOFF_OUT, 65536);
    cvt_kernel<<<(2359296 + 255) / 256, 256>>>(W1, w + WOFF_W1, 2359296);
    cvt_kernel<<<(2359296 + 255) / 256, 256>>>(W2, w + WOFF_W2, 2359296);

    // 1) LN1: x -> h (s2), tf32-rounded
    ln_kernel<<<T_TOK / 8, 256>>>(x, ln1_g, ln1_b, s2);

    // 2) QKV per channel: h[:,c*256:+256] @ W_qkv[c] + b_qkv[c] -> s1[T,3,768]
    for (int c = 0; c < 3; c++) {
        tgemm_kernel<0><<<dim3((3 * KFD) / BN, T_TOK / BM), 256, SMEM_BYTES>>>(
            KFD,
            s2 + c * KFD, H_DIM,
            w + WOFF_QKV + (size_t)c * KFD * 3 * KFD, 3 * KFD,
            s1 + c * 3 * KFD, C_CH * 3 * KFD,
            b_qkv + c * 3 * KFD, nullptr);
    }

    // 3) criss-cross attention: qkv(s1) -> ctx(s2) [T*3, 256], tf32-rounded
    attn_kernel<<<(T_TOK * KFD) / 256, 256>>>(s1, s2);

    // 4) out-proj + residual: ctx @ W_out + b_out + x -> xr  (rows = T*3)
    tgemm_kernel<1><<<dim3(KFD / BN, (T_TOK * C_CH) / BM), 256, SMEM_BYTES>>>(
        KFD, s2, KFD, w + WOFF_OUT, KFD, xr, KFD, b_out, x);

    // 5) LN2: xr -> y (s2), tf32-rounded
    ln_kernel<<<T_TOK / 8, 256>>>(xr, ln2_g, ln2_b, s2);

    // 6) MLP fc1 + exact GELU (tf32-rounded out): y @ W1 + b1 -> act (s1)
    tgemm_kernel<2><<<dim3(M_MLP / BN, T_TOK / BM), 256, SMEM_BYTES>>>(
        H_DIM, s2, H_DIM, w + WOFF_W1, M_MLP, s1, M_MLP, b1, nullptr);

    // 7) MLP fc2 + residual: act @ W2 + b2 + xr -> out
    tgemm_kernel<1><<<dim3(H_DIM / BN, T_TOK / BM), 256, SMEM_BYTES>>>(
        M_MLP, s1, M_MLP, w + WOFF_W2, H_DIM, out, H_DIM, b2, xr);
}

// round 5
// speedup vs baseline: 5.0598x; 1.7961x over previous
#include <cuda_runtime.h>
#include <cuda_fp16.h>
#include <math.h>
#include <stdint.h>

#define T_TOK 32768
#define H_DIM 768
#define C_CH  3
#define KFD   256
#define M_MLP 3072
#define LN_EPS 1e-6f

// ---- GEMM tiling (fp16 mma.sync m16n8k16) ----
#define GBM 128
#define GBN 256
#define BKH 64                    // halves per K-tile (128B of data per row)
#define STAGES 3
#define ROWB 144                  // padded smem row stride in bytes (16B-aligned, conflict-free)
#define ROWW 36                   // .. in 32-bit words
#define A_BYTES (GBM * ROWB)      // 18432
#define B_BYTES (GBN * ROWB)      // 36864
#define STAGE_BYTES (A_BYTES + B_BYTES)     // 55296
#define SMEMG_BYTES (STAGES * STAGE_BYTES)  // 165888

// Scratch (device globals; no allocations anywhere).
__device__ __align__(16) __half g_s1[(size_t)T_TOK * M_MLP];  // qkv [T,2304] then act [T,3072]
__device__ __align__(16) __half g_s2[(size_t)T_TOK * H_DIM];  // h / ctx / y
__device__ __align__(16) float  g_xr[(size_t)T_TOK * H_DIM];
// transposed fp16 weights (K-major rows [N,K]):
#define WOFF_QKV 0
#define WOFF_OUT 589824
#define WOFF_W1  655360
#define WOFF_W2  3014656
__device__ __align__(16) __half g_w[5373952];

// ---------------------------------------------------------------- helpers
__device__ __forceinline__ float gelu_exact(float x)
{
    return 0.5f * x * (1.0f + erff(x * 0.70710678118654752f));
}

__device__ __forceinline__ void cp16(void* dst_smem, const void* src)
{
    unsigned d = (unsigned)__cvta_generic_to_shared(dst_smem);
    asm volatile("cp.async.cg.shared.global [%0], [%1], 16;\n" :: "r"(d), "l"(src));
}

__device__ __forceinline__ void mma_f16(float* d, const uint32_t* a, const uint32_t* b)
{
    asm volatile(
        "mma.sync.aligned.m16n8k16.row.col.f32.f16.f16.f32 "
        "{%0,%1,%2,%3}, {%4,%5,%6,%7}, {%8,%9}, {%0,%1,%2,%3};\n"
        : "+f"(d[0]), "+f"(d[1]), "+f"(d[2]), "+f"(d[3])
        : "r"(a[0]), "r"(a[1]), "r"(a[2]), "r"(a[3]), "r"(b[0]), "r"(b[1]));
}

// ---------------------------------------------------------------- transpose+half
// in fp32 [K, N] -> out fp16 [N, K], blockIdx.z = batch
__global__ void transpose_h_kernel(const float* __restrict__ in,
                                   __half* __restrict__ out, int K, int N)
{
    __shared__ float t[32][33];
    size_t bo = (size_t)blockIdx.z * K * N;
    in += bo;
    out += bo;
    int k0 = blockIdx.y * 32, n0 = blockIdx.x * 32;
    int x = threadIdx.x, y = threadIdx.y;
#pragma unroll
    for (int i = 0; i < 32; i += 8)
        t[y + i][x] = in[(size_t)(k0 + y + i) * N + n0 + x];
    __syncthreads();
#pragma unroll
    for (int i = 0; i < 32; i += 8)
        out[(size_t)(n0 + y + i) * K + k0 + x] = __float2half_rn(t[x][y + i]);
}

// ---------------------------------------------------------------- LayerNorm -> half
__global__ void ln_kernel(const float* __restrict__ in,
                          const float* __restrict__ gam,
                          const float* __restrict__ bet,
                          __half* __restrict__ out)
{
    int gwarp = (blockIdx.x * blockDim.x + threadIdx.x) >> 5;
    int lane  = threadIdx.x & 31;
    if (gwarp >= T_TOK) return;
    const float* row = in + (size_t)gwarp * H_DIM;
    float v[24];
    float s = 0.f, sq = 0.f;
#pragma unroll
    for (int i = 0; i < 24; i++) {
        v[i] = row[lane + 32 * i];
        s += v[i];
        sq += v[i] * v[i];
    }
#pragma unroll
    for (int o = 16; o > 0; o >>= 1) {
        s  += __shfl_xor_sync(0xffffffffu, s,  o);
        sq += __shfl_xor_sync(0xffffffffu, sq, o);
    }
    float mu  = s * (1.0f / H_DIM);
    float var = fmaxf(sq * (1.0f / H_DIM) - mu * mu, 0.0f);
    float rs  = rsqrtf(var + LN_EPS);
    __half* orow = out + (size_t)gwarp * H_DIM;
#pragma unroll
    for (int i = 0; i < 24; i++) {
        int j = lane + 32 * i;
        orow[j] = __float2half_rn((v[i] - mu) * rs * gam[j] + bet[j]);
    }
}

// ------------------------------------------------- criss-cross attention core
// qkv half [T,2304]; ctx half [T*3,256]
__global__ void attn_kernel(const __half* __restrict__ qkv, __half* __restrict__ ctx)
{
    int gid = blockIdx.x * blockDim.x + threadIdx.x;
    int t  = gid >> 8;
    int kf = gid & 255;
    const __half* base = qkv + (size_t)t * (3 * H_DIM);
    float q[3], k[3], v[3];
#pragma unroll
    for (int c = 0; c < 3; c++) {
        q[c] = __half2float(base[c * H_DIM + kf]);
        k[c] = __half2float(base[c * H_DIM + KFD + kf]);
        v[c] = __half2float(base[c * H_DIM + 2 * KFD + kf]);
    }
    const float scale = 0.0625f;
    float o0 = 0.f, o1 = 0.f, o2 = 0.f;
#pragma unroll
    for (int c = 0; c < 3; c++) {
        float s0 = q[c] * k[0] * scale;
        float s1 = q[c] * k[1] * scale;
        float s2 = q[c] * k[2] * scale;
        float m  = fmaxf(s0, fmaxf(s1, s2));
        float e0 = __expf(s0 - m), e1 = __expf(s1 - m), e2 = __expf(s2 - m);
        float inv = v[c] / (e0 + e1 + e2);
        o0 = fmaf(e0, inv, o0);
        o1 = fmaf(e1, inv, o1);
        o2 = fmaf(e2, inv, o2);
    }
    size_t ob = (size_t)t * 3 * KFD + kf;
    ctx[ob]           = __float2half_rn(o0);
    ctx[ob + KFD]     = __float2half_rn(o1);
    ctx[ob + 2 * KFD] = __float2half_rn(o2);
}

// ---------------------------------------------------------------- FP16 GEMM
// C[M,N] = A[M,K] @ BT[N,K]^T (+bias / +bias+res / gelu(+bias))
// A, BT: half, K-major rows. CTA 128x256, BK=64 halves, 3-stage cp.async.
// 8 warps (2x4), warp tile 64x64, fp32 accumulators.
// EPI 0: +bias -> half out; EPI 1: +bias+res -> float out; EPI 2: gelu -> half out
template <int EPI, typename TO>
__global__ void __launch_bounds__(256, 1)
hgemm_kernel(int K,
             const __half* __restrict__ A, int lda,
             const __half* __restrict__ BT, int ldb,
             TO* __restrict__ C, int ldc,
             const float* __restrict__ bias,
             const float* __restrict__ res)
{
    extern __shared__ char smem[];

    const int tid  = threadIdx.x;
    const int wid  = tid >> 5;
    const int lane = tid & 31;
    const int gID  = lane >> 2;
    const int tig  = lane & 3;
    const int wm   = (wid >> 2) * 64;
    const int wn   = (wid & 3) * 64;
    const int row0 = blockIdx.y * GBM;
    const int col0 = blockIdx.x * GBN;

    const __half* Ag = A + (size_t)row0 * lda;
    const __half* Bg = BT + (size_t)col0 * ldb;

    float acc[4][8][4];
#pragma unroll
    for (int mi = 0; mi < 4; mi++)
#pragma unroll
        for (int ni = 0; ni < 8; ni++)
#pragma unroll
            for (int j = 0; j < 4; j++) acc[mi][ni][j] = 0.f;

    const int nk = K / BKH;

    // prologue
#pragma unroll
    for (int s = 0; s < STAGES - 1; s++) {
        char* as = smem + s * STAGE_BYTES;
        char* bs = as + A_BYTES;
        int k0 = s * BKH;
#pragma unroll
        for (int i = 0; i < 4; i++) {
            int id = tid + 256 * i;
            int r = id >> 3, c = id & 7;
            cp16(as + r * ROWB + c * 16, Ag + (size_t)r * lda + k0 + c * 8);
        }
#pragma unroll
        for (int i = 0; i < 8; i++) {
            int id = tid + 256 * i;
            int n = id >> 3, c = id & 7;
            cp16(bs + n * ROWB + c * 16, Bg + (size_t)n * ldb + k0 + c * 8);
        }
        asm volatile("cp.async.commit_group;\n");
    }

    for (int kt = 0; kt < nk; kt++) {
        asm volatile("cp.async.wait_group %0;\n" :: "n"(STAGES - 2));
        __syncthreads();

        {
            int kf = kt + STAGES - 1;
            if (kf < nk) {
                int buf = kf % STAGES;
                char* as = smem + buf * STAGE_BYTES;
                char* bs = as + A_BYTES;
                int k0 = kf * BKH;
#pragma unroll
                for (int i = 0; i < 4; i++) {
                    int id = tid + 256 * i;
                    int r = id >> 3, c = id & 7;
                    cp16(as + r * ROWB + c * 16, Ag + (size_t)r * lda + k0 + c * 8);
                }
#pragma unroll
                for (int i = 0; i < 8; i++) {
                    int id = tid + 256 * i;
                    int n = id >> 3, c = id & 7;
                    cp16(bs + n * ROWB + c * 16, Bg + (size_t)n * ldb + k0 + c * 8);
                }
            }
            asm volatile("cp.async.commit_group;\n");
        }

        const uint32_t* as32 = (const uint32_t*)(smem + (kt % STAGES) * STAGE_BYTES);
        const uint32_t* bs32 = (const uint32_t*)((const char*)as32 + A_BYTES);
#pragma unroll
        for (int ks2 = 0; ks2 < 32; ks2 += 8) {   // k-step of 16 halves = 8 words
            uint32_t af[4][4], bf[8][2];
#pragma unroll
            for (int mi = 0; mi < 4; mi++) {
                int m = wm + mi * 16 + gID;
                const uint32_t* p = as32 + m * ROWW + ks2 + tig;
                af[mi][0] = p[0];
                af[mi][1] = p[8 * ROWW];     // row m+8
                af[mi][2] = p[4];            // k+8
                af[mi][3] = p[8 * ROWW + 4];
            }
#pragma unroll
            for (int ni = 0; ni < 8; ni++) {
                int n = wn + ni * 8 + gID;
                const uint32_t* p = bs32 + n * ROWW + ks2 + tig;
                bf[ni][0] = p[0];
                bf[ni][1] = p[4];
            }
#pragma unroll
            for (int mi = 0; mi < 4; mi++)
#pragma unroll
                for (int ni = 0; ni < 8; ni++)
                    mma_f16(acc[mi][ni], af[mi], bf[ni]);
        }
        __syncthreads();
    }

    // epilogue
#pragma unroll
    for (int mi = 0; mi < 4; mi++) {
#pragma unroll
        for (int ni = 0; ni < 8; ni++) {
            int c = col0 + wn + ni * 8 + tig * 2;
            float2 bv = *(const float2*)(bias + c);
#pragma unroll
            for (int h = 0; h < 2; h++) {
                int r = row0 + wm + mi * 16 + gID + h * 8;
                float v0 = acc[mi][ni][h * 2 + 0] + bv.x;
                float v1 = acc[mi][ni][h * 2 + 1] + bv.y;
                if (EPI == 1) {
                    float2 rv = *(const float2*)(res + (size_t)r * ldc + c);
                    v0 += rv.x;
                    v1 += rv.y;
                    *(float2*)((float*)C + (size_t)r * ldc + c) = make_float2(v0, v1);
                } else if (EPI == 2) {
                    __half2 o = __floats2half2_rn(gelu_exact(v0), gelu_exact(v1));
                    *(__half2*)((__half*)C + (size_t)r * ldc + c) = o;
                } else {
                    __half2 o = __floats2half2_rn(v0, v1);
                    *(__half2*)((__half*)C + (size_t)r * ldc + c) = o;
                }
            }
        }
    }
}

// ---------------------------------------------------------------- launch
extern "C" void kernel_launch(void* const* d_in, const int* in_sizes, int n_in,
                              void* d_out, int out_size)
{
    const float* x     = (const float*)d_in[0];
    const float* W_qkv = (const float*)d_in[1];
    const float* b_qkv = (const float*)d_in[2];
    const float* W_out = (const float*)d_in[3];
    const float* b_out = (const float*)d_in[4];
    const float* ln1_g = (const float*)d_in[5];
    const float* ln1_b = (const float*)d_in[6];
    const float* ln2_g = (const float*)d_in[7];
    const float* ln2_b = (const float*)d_in[8];
    const float* W1    = (const float*)d_in[9];
    const float* b1    = (const float*)d_in[10];
    const float* W2    = (const float*)d_in[11];
    const float* b2    = (const float*)d_in[12];
    float* out = (float*)d_out;

    __half *s1, *s2, *w;
    float *xr;
    cudaGetSymbolAddress((void**)&s1, g_s1);
    cudaGetSymbolAddress((void**)&s2, g_s2);
    cudaGetSymbolAddress((void**)&xr, g_xr);
    cudaGetSymbolAddress((void**)&w,  g_w);

    cudaFuncSetAttribute((const void*)hgemm_kernel<0, __half>,
                         cudaFuncAttributeMaxDynamicSharedMemorySize, SMEMG_BYTES);
    cudaFuncSetAttribute((const void*)hgemm_kernel<1, float>,
                         cudaFuncAttributeMaxDynamicSharedMemorySize, SMEMG_BYTES);
    cudaFuncSetAttribute((const void*)hgemm_kernel<2, __half>,
                         cudaFuncAttributeMaxDynamicSharedMemorySize, SMEMG_BYTES);

    // 0) transpose + fp16-round all weights: W[K,N] -> WT[N,K]
    transpose_h_kernel<<<dim3(768 / 32, 256 / 32, 3), dim3(32, 8)>>>(W_qkv, w + WOFF_QKV, 256, 768);
    transpose_h_kernel<<<dim3(256 / 32, 256 / 32, 1), dim3(32, 8)>>>(W_out, w + WOFF_OUT, 256, 256);
    transpose_h_kernel<<<dim3(3072 / 32, 768 / 32, 1), dim3(32, 8)>>>(W1, w + WOFF_W1, 768, 3072);
    transpose_h_kernel<<<dim3(768 / 32, 3072 / 32, 1), dim3(32, 8)>>>(W2, w + WOFF_W2, 3072, 768);

    // 1) LN1: x -> h (s2, half)
    ln_kernel<<<T_TOK / 8, 256>>>(x, ln1_g, ln1_b, s2);

    // 2) QKV per channel: [32768,256] @ [256,768] -> s1[T,2304] half
    for (int c = 0; c < 3; c++) {
        hgemm_kernel<0, __half><<<dim3(3, 256), 256, SMEMG_BYTES>>>(
            KFD,
            s2 + c * KFD, H_DIM,
            w + WOFF_QKV + (size_t)c * 768 * 256, KFD,
            s1 + c * 768, 2304,
            b_qkv + c * 768, nullptr);
    }

    // 3) attention: qkv(s1) -> ctx(s2) [T*3, 256] half
    attn_kernel<<<(T_TOK * KFD) / 256, 256>>>(s1, s2);

    // 4) out-proj + residual: [98304,256] @ [256,256] + x -> xr (fp32)
    hgemm_kernel<1, float><<<dim3(1, 768), 256, SMEMG_BYTES>>>(
        KFD, s2, KFD, w + WOFF_OUT, KFD, xr, KFD, b_out, x);

    // 5) LN2: xr -> y (s2, half)
    ln_kernel<<<T_TOK / 8, 256>>>(xr, ln2_g, ln2_b, s2);

    // 6) MLP fc1 + GELU: [32768,768] @ [768,3072] -> act (s1, half)
    hgemm_kernel<2, __half><<<dim3(12, 256), 256, SMEMG_BYTES>>>(
        H_DIM, s2, H_DIM, w + WOFF_W1, H_DIM, s1, M_MLP, b1, nullptr);

    // 7) MLP fc2 + residual: [32768,3072] @ [3072,768] + xr -> out (fp32)
    hgemm_kernel<1, float><<<dim3(3, 256), 256, SMEMG_BYTES>>>(
        M_MLP, s1, M_MLP, w + WOFF_W2, M_MLP, out, H_DIM, b2, xr);
}

// round 7
// speedup vs baseline: 5.4260x; 1.0724x over previous
#include <cuda_runtime.h>
#include <cuda_fp16.h>
#include <math.h>
#include <stdint.h>

#define T_TOK 32768
#define H_DIM 768
#define C_CH  3
#define KFD   256
#define M_MLP 3072
#define LN_EPS 1e-6f

// ---- GEMM tiling (fp16 mma.sync m16n8k16, swizzled smem, ldmatrix) ----
#define GBM 128
#define GBN 256
#define BKH 64                     // halves per K-tile (128B rows)
#define STAGES 4
#define A_BYTES (GBM * 128)        // 16384
#define B_BYTES (GBN * 128)        // 32768
#define STAGE_BYTES (A_BYTES + B_BYTES)     // 49152
#define SMEMG_BYTES (STAGES * STAGE_BYTES)  // 196608

// Scratch (device globals; no allocations anywhere).
__device__ __align__(16) __half g_s1[(size_t)T_TOK * M_MLP];  // qkv [T,2304] then act [T,3072]
__device__ __align__(16) __half g_s2[(size_t)T_TOK * H_DIM];  // h / ctx / y
__device__ __align__(16) float  g_xr[(size_t)T_TOK * H_DIM];
// transposed fp16 weights (K-major rows [N,K]):
#define WOFF_QKV 0
#define WOFF_OUT 589824
#define WOFF_W1  655360
#define WOFF_W2  3014656
__device__ __align__(16) __half g_w[5373952];

// ---------------------------------------------------------------- helpers
__device__ __forceinline__ float gelu_exact(float x)
{
    return 0.5f * x * (1.0f + erff(x * 0.70710678118654752f));
}

__device__ __forceinline__ void cp16(uint32_t dst_smem, const void* src)
{
    asm volatile("cp.async.cg.shared.global [%0], [%1], 16;\n" :: "r"(dst_smem), "l"(src));
}

__device__ __forceinline__ void ldsm4(uint32_t* r, uint32_t addr)
{
    asm volatile("ldmatrix.sync.aligned.m8n8.x4.shared.b16 {%0,%1,%2,%3}, [%4];"
                 : "=r"(r[0]), "=r"(r[1]), "=r"(r[2]), "=r"(r[3]) : "r"(addr));
}

__device__ __forceinline__ void mma_f16(float* d, const uint32_t* a,
                                        uint32_t b0, uint32_t b1)
{
    asm volatile(
        "mma.sync.aligned.m16n8k16.row.col.f32.f16.f16.f32 "
        "{%0,%1,%2,%3}, {%4,%5,%6,%7}, {%8,%9}, {%0,%1,%2,%3};\n"
        : "+f"(d[0]), "+f"(d[1]), "+f"(d[2]), "+f"(d[3])
        : "r"(a[0]), "r"(a[1]), "r"(a[2]), "r"(a[3]), "r"(b0), "r"(b1));
}

// ---------------------------------------------------------------- transpose+half
__global__ void transpose_h_kernel(const float* __restrict__ in,
                                   __half* __restrict__ out, int K, int N)
{
    __shared__ float t[32][33];
    size_t bo = (size_t)blockIdx.z * K * N;
    in += bo;
    out += bo;
    int k0 = blockIdx.y * 32, n0 = blockIdx.x * 32;
    int x = threadIdx.x, y = threadIdx.y;
#pragma unroll
    for (int i = 0; i < 32; i += 8)
        t[y + i][x] = in[(size_t)(k0 + y + i) * N + n0 + x];
    __syncthreads();
#pragma unroll
    for (int i = 0; i < 32; i += 8)
        out[(size_t)(n0 + y + i) * K + k0 + x] = __float2half_rn(t[x][y + i]);
}

// ---------------------------------------------------------------- LayerNorm -> half
__global__ void ln_kernel(const float* __restrict__ in,
                          const float* __restrict__ gam,
                          const float* __restrict__ bet,
                          __half* __restrict__ out)
{
    int gwarp = (blockIdx.x * blockDim.x + threadIdx.x) >> 5;
    int lane  = threadIdx.x & 31;
    if (gwarp >= T_TOK) return;
    const float* row = in + (size_t)gwarp * H_DIM;
    float v[24];
    float s = 0.f, sq = 0.f;
#pragma unroll
    for (int i = 0; i < 24; i++) {
        v[i] = row[lane + 32 * i];
        s += v[i];
        sq += v[i] * v[i];
    }
#pragma unroll
    for (int o = 16; o > 0; o >>= 1) {
        s  += __shfl_xor_sync(0xffffffffu, s,  o);
        sq += __shfl_xor_sync(0xffffffffu, sq, o);
    }
    float mu  = s * (1.0f / H_DIM);
    float var = fmaxf(sq * (1.0f / H_DIM) - mu * mu, 0.0f);
    float rs  = rsqrtf(var + LN_EPS);
    __half* orow = out + (size_t)gwarp * H_DIM;
#pragma unroll
    for (int i = 0; i < 24; i++) {
        int j = lane + 32 * i;
        orow[j] = __float2half_rn((v[i] - mu) * rs * gam[j] + bet[j]);
    }
}

// ------------------------------------------------- criss-cross attention core
__global__ void attn_kernel(const __half* __restrict__ qkv, __half* __restrict__ ctx)
{
    int gid = blockIdx.x * blockDim.x + threadIdx.x;
    int t  = gid >> 8;
    int kf = gid & 255;
    const __half* base = qkv + (size_t)t * (3 * H_DIM);
    float q[3], k[3], v[3];
#pragma unroll
    for (int c = 0; c < 3; c++) {
        q[c] = __half2float(base[c * H_DIM + kf]);
        k[c] = __half2float(base[c * H_DIM + KFD + kf]);
        v[c] = __half2float(base[c * H_DIM + 2 * KFD + kf]);
    }
    const float scale = 0.0625f;
    float o0 = 0.f, o1 = 0.f, o2 = 0.f;
#pragma unroll
    for (int c = 0; c < 3; c++) {
        float s0 = q[c] * k[0] * scale;
        float s1 = q[c] * k[1] * scale;
        float s2 = q[c] * k[2] * scale;
        float m  = fmaxf(s0, fmaxf(s1, s2));
        float e0 = __expf(s0 - m), e1 = __expf(s1 - m), e2 = __expf(s2 - m);
        float inv = v[c] / (e0 + e1 + e2);
        o0 = fmaf(e0, inv, o0);
        o1 = fmaf(e1, inv, o1);
        o2 = fmaf(e2, inv, o2);
    }
    size_t ob = (size_t)t * 3 * KFD + kf;
    ctx[ob]           = __float2half_rn(o0);
    ctx[ob + KFD]     = __float2half_rn(o1);
    ctx[ob + 2 * KFD] = __float2half_rn(o2);
}

// ---------------------------------------------------------------- FP16 GEMM
// C[M,N] = A[M,K] @ BT[N,K]^T (+bias / +bias+res / gelu(+bias))
// SW128-swizzled smem (128B rows), ldmatrix fragments, double-buffered,
// 4-stage cp.async. gridDim.z batches independent GEMMs (stride az/bz/cz/biasz).
template <int EPI, typename TO>
__global__ void __launch_bounds__(256, 1)
hgemm_kernel(int K,
             const __half* __restrict__ A, int lda, size_t az,
             const __half* __restrict__ BT, int ldb, size_t bz,
             TO* __restrict__ C, int ldc, size_t cz,
             const float* __restrict__ bias, size_t biasz,
             const float* __restrict__ res)
{
    extern __shared__ char smem[];
    const uint32_t sbase = (uint32_t)__cvta_generic_to_shared(smem);

    const int tid  = threadIdx.x;
    const int wid  = tid >> 5;
    const int lane = tid & 31;
    const int gID  = lane >> 2;
    const int tig  = lane & 3;
    const int wm   = (wid >> 2) * 64;
    const int wn   = (wid & 3) * 64;
    const int row0 = blockIdx.y * GBM;
    const int col0 = blockIdx.x * GBN;

    A   += (size_t)blockIdx.z * az;
    BT  += (size_t)blockIdx.z * bz;
    C   += (size_t)blockIdx.z * cz;
    bias += (size_t)blockIdx.z * biasz;

    const __half* Ag = A + (size_t)row0 * lda;
    const __half* Bg = BT + (size_t)col0 * ldb;

    // copy mapping: A: 4 chunks/thread, B: 8 chunks/thread (16B chunks, swizzled)
    const int cr = tid >> 3;          // row (A: +0, B: +0/128)
    const int cc = tid & 7;           // logical chunk

    // ldmatrix lane geometry
    const int lrA = wm + (lane & 15);        // A row (+ mi*16)
    const int lrB = wn + (lane & 15);        // B row (+ pair*16)
    const int hi  = lane >> 4;               // chunk-half select
    const int sxA = lrA & 7;
    const int sxB = lrB & 7;

    float acc[4][8][4];
#pragma unroll
    for (int mi = 0; mi < 4; mi++)
#pragma unroll
        for (int ni = 0; ni < 8; ni++)
#pragma unroll
            for (int j = 0; j < 4; j++) acc[mi][ni][j] = 0.f;

    const int nk = K / BKH;

    // prologue: stages 0..STAGES-2
#pragma unroll
    for (int s = 0; s < STAGES - 1; s++) {
        if (s < nk) {
            uint32_t as = sbase + s * STAGE_BYTES;
            uint32_t bs = as + A_BYTES;
            int k0 = s * BKH;
#pragma unroll
            for (int i = 0; i < 4; i++) {
                int r = cr, c = cc;
                if (i >= 2) r += 64;
                if (i & 1) { }
                // A has 1024 chunks: thread covers rows cr, cr+32, cr+64, cr+96
                r = cr + 32 * i;
                cp16(as + r * 128 + ((c ^ (r & 7)) << 4),
                     Ag + (size_t)r * lda + k0 + c * 8);
            }
#pragma unroll
            for (int i = 0; i < 8; i++) {
                int r = cr + 32 * i, c = cc;
                cp16(bs + r * 128 + ((c ^ (r & 7)) << 4),
                     Bg + (size_t)r * ldb + k0 + c * 8);
            }
        }
        asm volatile("cp.async.commit_group;\n");
    }

    for (int kt = 0; kt < nk; kt++) {
        asm volatile("cp.async.wait_group %0;\n" :: "n"(STAGES - 2));
        __syncthreads();

        // issue stage kt+STAGES-1
        {
            int kf = kt + STAGES - 1;
            if (kf < nk) {
                uint32_t as = sbase + (kf % STAGES) * STAGE_BYTES;
                uint32_t bs = as + A_BYTES;
                int k0 = kf * BKH;
#pragma unroll
                for (int i = 0; i < 4; i++) {
                    int r = cr + 32 * i, c = cc;
                    cp16(as + r * 128 + ((c ^ (r & 7)) << 4),
                         Ag + (size_t)r * lda + k0 + c * 8);
                }
#pragma unroll
                for (int i = 0; i < 8; i++) {
                    int r = cr + 32 * i, c = cc;
                    cp16(bs + r * 128 + ((c ^ (r & 7)) << 4),
                         Bg + (size_t)r * ldb + k0 + c * 8);
                }
            }
            asm volatile("cp.async.commit_group;\n");
        }

        const uint32_t abase = sbase + (kt % STAGES) * STAGE_BYTES + lrA * 128;
        const uint32_t bbase = sbase + (kt % STAGES) * STAGE_BYTES + A_BYTES + lrB * 128;

        uint32_t af[2][4][4], bf[2][4][4];
        // load k-step 0 fragments
        {
            uint32_t chA = (uint32_t)((hi ^ sxA) << 4);
            uint32_t chB = (uint32_t)((hi ^ sxB) << 4);
#pragma unroll
            for (int mi = 0; mi < 4; mi++) ldsm4(af[0][mi], abase + mi * 2048 + chA);
#pragma unroll
            for (int p = 0; p < 4; p++) ldsm4(bf[0][p], bbase + p * 2048 + chB);
        }
#pragma unroll
        for (int s = 0; s < 4; s++) {
            int cur = s & 1, nxt = cur ^ 1;
            if (s < 3) {
                uint32_t chA = (uint32_t)(((2 * (s + 1) + hi) ^ sxA) << 4);
                uint32_t chB = (uint32_t)(((2 * (s + 1) + hi) ^ sxB) << 4);
#pragma unroll
                for (int mi = 0; mi < 4; mi++) ldsm4(af[nxt][mi], abase + mi * 2048 + chA);
#pragma unroll
                for (int p = 0; p < 4; p++) ldsm4(bf[nxt][p], bbase + p * 2048 + chB);
            }
#pragma unroll
            for (int mi = 0; mi < 4; mi++)
#pragma unroll
                for (int p = 0; p < 4; p++) {
                    mma_f16(acc[mi][2 * p],     af[cur][mi], bf[cur][p][0], bf[cur][p][2]);
                    mma_f16(acc[mi][2 * p + 1], af[cur][mi], bf[cur][p][1], bf[cur][p][3]);
                }
        }
        __syncthreads();
    }

    // epilogue
#pragma unroll
    for (int mi = 0; mi < 4; mi++) {
#pragma unroll
        for (int ni = 0; ni < 8; ni++) {
            int c = col0 + wn + ni * 8 + tig * 2;
            float2 bv = *(const float2*)(bias + c);
#pragma unroll
            for (int h = 0; h < 2; h++) {
                int r = row0 + wm + mi * 16 + gID + h * 8;
                float v0 = acc[mi][ni][h * 2 + 0] + bv.x;
                float v1 = acc[mi][ni][h * 2 + 1] + bv.y;
                if (EPI == 1) {
                    float2 rv = *(const float2*)(res + (size_t)r * ldc + c);
                    v0 += rv.x;
                    v1 += rv.y;
                    *(float2*)((float*)C + (size_t)r * ldc + c) = make_float2(v0, v1);
                } else if (EPI == 2) {
                    __half2 o = __floats2half2_rn(gelu_exact(v0), gelu_exact(v1));
                    *(__half2*)((__half*)C + (size_t)r * ldc + c) = o;
                } else {
                    __half2 o = __floats2half2_rn(v0, v1);
                    *(__half2*)((__half*)C + (size_t)r * ldc + c) = o;
                }
            }
        }
    }
}

// ---------------------------------------------------------------- launch
extern "C" void kernel_launch(void* const* d_in, const int* in_sizes, int n_in,
                              void* d_out, int out_size)
{
    const float* x     = (const float*)d_in[0];
    const float* W_qkv = (const float*)d_in[1];
    const float* b_qkv = (const float*)d_in[2];
    const float* W_out = (const float*)d_in[3];
    const float* b_out = (const float*)d_in[4];
    const float* ln1_g = (const float*)d_in[5];
    const float* ln1_b = (const float*)d_in[6];
    const float* ln2_g = (const float*)d_in[7];
    const float* ln2_b = (const float*)d_in[8];
    const float* W1    = (const float*)d_in[9];
    const float* b1    = (const float*)d_in[10];
    const float* W2    = (const float*)d_in[11];
    const float* b2    = (const float*)d_in[12];
    float* out = (float*)d_out;

    __half *s1, *s2, *w;
    float *xr;
    cudaGetSymbolAddress((void**)&s1, g_s1);
    cudaGetSymbolAddress((void**)&s2, g_s2);
    cudaGetSymbolAddress((void**)&xr, g_xr);
    cudaGetSymbolAddress((void**)&w,  g_w);

    cudaFuncSetAttribute((const void*)hgemm_kernel<0, __half>,
                         cudaFuncAttributeMaxDynamicSharedMemorySize, SMEMG_BYTES);
    cudaFuncSetAttribute((const void*)hgemm_kernel<1, float>,
                         cudaFuncAttributeMaxDynamicSharedMemorySize, SMEMG_BYTES);
    cudaFuncSetAttribute((const void*)hgemm_kernel<2, __half>,
                         cudaFuncAttributeMaxDynamicSharedMemorySize, SMEMG_BYTES);

    // 0) transpose + fp16-round all weights: W[K,N] -> WT[N,K]
    transpose_h_kernel<<<dim3(768 / 32, 256 / 32, 3), dim3(32, 8)>>>(W_qkv, w + WOFF_QKV, 256, 768);
    transpose_h_kernel<<<dim3(256 / 32, 256 / 32, 1), dim3(32, 8)>>>(W_out, w + WOFF_OUT, 256, 256);
    transpose_h_kernel<<<dim3(3072 / 32, 768 / 32, 1), dim3(32, 8)>>>(W1, w + WOFF_W1, 768, 3072);
    transpose_h_kernel<<<dim3(768 / 32, 3072 / 32, 1), dim3(32, 8)>>>(W2, w + WOFF_W2, 3072, 768);

    // 1) LN1: x -> h (s2, half)
    ln_kernel<<<T_TOK / 8, 256>>>(x, ln1_g, ln1_b, s2);

    // 2) QKV (all 3 channels, gridDim.z=3): [32768,256] @ [256,768] -> s1[T,2304]
    hgemm_kernel<0, __half><<<dim3(3, 256, 3), 256, SMEMG_BYTES>>>(
        KFD,
        s2, H_DIM, (size_t)KFD,
        w + WOFF_QKV, KFD, (size_t)768 * 256,
        s1, 2304, (size_t)768,
        b_qkv, (size_t)768,
        nullptr);

    // 3) attention: qkv(s1) -> ctx(s2) [T*3, 256] half
    attn_kernel<<<(T_TOK * KFD) / 256, 256>>>(s1, s2);

    // 4) out-proj + residual: [98304,256] @ [256,256] + x -> xr (fp32)
    hgemm_kernel<1, float><<<dim3(1, 768, 1), 256, SMEMG_BYTES>>>(
        KFD, s2, KFD, 0, w + WOFF_OUT, KFD, 0, xr, KFD, 0, b_out, 0, x);

    // 5) LN2: xr -> y (s2, half)
    ln_kernel<<<T_TOK / 8, 256>>>(xr, ln2_g, ln2_b, s2);

    // 6) MLP fc1 + GELU: [32768,768] @ [768,3072] -> act (s1, half)
    hgemm_kernel<2, __half><<<dim3(12, 256, 1), 256, SMEMG_BYTES>>>(
        H_DIM, s2, H_DIM, 0, w + WOFF_W1, H_DIM, 0, s1, M_MLP, 0, b1, 0, nullptr);

    // 7) MLP fc2 + residual: [32768,3072] @ [3072,768] + xr -> out (fp32)
    hgemm_kernel<1, float><<<dim3(3, 256, 1), 256, SMEMG_BYTES>>>(
        M_MLP, s1, M_MLP, 0, w + WOFF_W2, M_MLP, 0, out, H_DIM, 0, b2, 0, xr);
}

// round 8
// speedup vs baseline: 5.9494x; 1.0965x over previous
#include <cuda_runtime.h>
#include <cuda_fp16.h>
#include <math.h>
#include <stdint.h>

#define T_TOK 32768
#define H_DIM 768
#define C_CH  3
#define KFD   256
#define M_MLP 3072
#define LN_EPS 1e-6f

// ---- GEMM tiling (fp16 mma.sync m16n8k16, swizzled smem, ldmatrix) ----
#define GBM 128
#define GBN 128
#define BKH 64                     // halves per K-tile (128B rows)
#define STAGES 3
#define A_BYTES (GBM * 128)        // 16384
#define B_BYTES (GBN * 128)        // 16384
#define STAGE_BYTES (A_BYTES + B_BYTES)     // 32768
#define SMEMG_BYTES (STAGES * STAGE_BYTES)  // 98304

// Scratch (device globals; no allocations anywhere).
__device__ __align__(16) __half g_s1[(size_t)T_TOK * M_MLP];  // qkv [T,2304] then act [T,3072]
__device__ __align__(16) __half g_s2[(size_t)T_TOK * H_DIM];  // h / ctx / y
__device__ __align__(16) float  g_xr[(size_t)T_TOK * H_DIM];
// transposed fp16 weights (K-major rows [N,K]):
#define WOFF_QKV 0
#define WOFF_OUT 589824
#define WOFF_W1  655360
#define WOFF_W2  3014656
__device__ __align__(16) __half g_w[5373952];

// ---------------------------------------------------------------- helpers
__device__ __forceinline__ float gelu_exact(float x)
{
    return 0.5f * x * (1.0f + erff(x * 0.70710678118654752f));
}

__device__ __forceinline__ void cp16(uint32_t dst_smem, const void* src)
{
    asm volatile("cp.async.cg.shared.global [%0], [%1], 16;\n" :: "r"(dst_smem), "l"(src));
}

__device__ __forceinline__ void ldsm4(uint32_t* r, uint32_t addr)
{
    asm volatile("ldmatrix.sync.aligned.m8n8.x4.shared.b16 {%0,%1,%2,%3}, [%4];"
                 : "=r"(r[0]), "=r"(r[1]), "=r"(r[2]), "=r"(r[3]) : "r"(addr));
}

__device__ __forceinline__ void mma_f16(float* d, const uint32_t* a,
                                        uint32_t b0, uint32_t b1)
{
    asm volatile(
        "mma.sync.aligned.m16n8k16.row.col.f32.f16.f16.f32 "
        "{%0,%1,%2,%3}, {%4,%5,%6,%7}, {%8,%9}, {%0,%1,%2,%3};\n"
        : "+f"(d[0]), "+f"(d[1]), "+f"(d[2]), "+f"(d[3])
        : "r"(a[0]), "r"(a[1]), "r"(a[2]), "r"(a[3]), "r"(b0), "r"(b1));
}

// ---------------------------------------------------------------- transpose+half
__global__ void transpose_h_kernel(const float* __restrict__ in,
                                   __half* __restrict__ out, int K, int N)
{
    __shared__ float t[32][33];
    size_t bo = (size_t)blockIdx.z * K * N;
    in += bo;
    out += bo;
    int k0 = blockIdx.y * 32, n0 = blockIdx.x * 32;
    int x = threadIdx.x, y = threadIdx.y;
#pragma unroll
    for (int i = 0; i < 32; i += 8)
        t[y + i][x] = in[(size_t)(k0 + y + i) * N + n0 + x];
    __syncthreads();
#pragma unroll
    for (int i = 0; i < 32; i += 8)
        out[(size_t)(n0 + y + i) * K + k0 + x] = __float2half_rn(t[x][y + i]);
}

// ---------------------------------------------------------------- LayerNorm -> half
__global__ void ln_kernel(const float* __restrict__ in,
                          const float* __restrict__ gam,
                          const float* __restrict__ bet,
                          __half* __restrict__ out)
{
    int gwarp = (blockIdx.x * blockDim.x + threadIdx.x) >> 5;
    int lane  = threadIdx.x & 31;
    if (gwarp >= T_TOK) return;
    const float* row = in + (size_t)gwarp * H_DIM;
    float v[24];
    float s = 0.f, sq = 0.f;
#pragma unroll
    for (int i = 0; i < 24; i++) {
        v[i] = row[lane + 32 * i];
        s += v[i];
        sq += v[i] * v[i];
    }
#pragma unroll
    for (int o = 16; o > 0; o >>= 1) {
        s  += __shfl_xor_sync(0xffffffffu, s,  o);
        sq += __shfl_xor_sync(0xffffffffu, sq, o);
    }
    float mu  = s * (1.0f / H_DIM);
    float var = fmaxf(sq * (1.0f / H_DIM) - mu * mu, 0.0f);
    float rs  = rsqrtf(var + LN_EPS);
    __half* orow = out + (size_t)gwarp * H_DIM;
#pragma unroll
    for (int i = 0; i < 24; i++) {
        int j = lane + 32 * i;
        orow[j] = __float2half_rn((v[i] - mu) * rs * gam[j] + bet[j]);
    }
}

// ------------------------------------------------- criss-cross attention core
__global__ void attn_kernel(const __half* __restrict__ qkv, __half* __restrict__ ctx)
{
    int gid = blockIdx.x * blockDim.x + threadIdx.x;
    int t  = gid >> 8;
    int kf = gid & 255;
    const __half* base = qkv + (size_t)t * (3 * H_DIM);
    float q[3], k[3], v[3];
#pragma unroll
    for (int c = 0; c < 3; c++) {
        q[c] = __half2float(base[c * H_DIM + kf]);
        k[c] = __half2float(base[c * H_DIM + KFD + kf]);
        v[c] = __half2float(base[c * H_DIM + 2 * KFD + kf]);
    }
    const float scale = 0.0625f;
    float o0 = 0.f, o1 = 0.f, o2 = 0.f;
#pragma unroll
    for (int c = 0; c < 3; c++) {
        float s0 = q[c] * k[0] * scale;
        float s1 = q[c] * k[1] * scale;
        float s2 = q[c] * k[2] * scale;
        float m  = fmaxf(s0, fmaxf(s1, s2));
        float e0 = __expf(s0 - m), e1 = __expf(s1 - m), e2 = __expf(s2 - m);
        float inv = v[c] / (e0 + e1 + e2);
        o0 = fmaf(e0, inv, o0);
        o1 = fmaf(e1, inv, o1);
        o2 = fmaf(e2, inv, o2);
    }
    size_t ob = (size_t)t * 3 * KFD + kf;
    ctx[ob]           = __float2half_rn(o0);
    ctx[ob + KFD]     = __float2half_rn(o1);
    ctx[ob + 2 * KFD] = __float2half_rn(o2);
}

// ---------------------------------------------------------------- FP16 GEMM
// C[M,N] = A[M,K] @ BT[N,K]^T (+bias / +bias+res / gelu(+bias))
// CTA 128x128, 128 threads (4 warps, 2x2 of 64x64), 3-stage cp.async,
// 96KB smem -> 2 CTAs/SM. SW128-swizzled rows, ldmatrix, frag double-buffer.
template <int EPI, typename TO>
__global__ void __launch_bounds__(128, 2)
hgemm_kernel(int K,
             const __half* __restrict__ A, int lda, size_t az,
             const __half* __restrict__ BT, int ldb, size_t bz,
             TO* __restrict__ C, int ldc, size_t cz,
             const float* __restrict__ bias, size_t biasz,
             const float* __restrict__ res)
{
    extern __shared__ char smem[];
    const uint32_t sbase = (uint32_t)__cvta_generic_to_shared(smem);

    const int tid  = threadIdx.x;
    const int wid  = tid >> 5;
    const int lane = tid & 31;
    const int gID  = lane >> 2;
    const int tig  = lane & 3;
    const int wm   = (wid >> 1) * 64;
    const int wn   = (wid & 1) * 64;
    const int row0 = blockIdx.y * GBM;
    const int col0 = blockIdx.x * GBN;

    A    += (size_t)blockIdx.z * az;
    BT   += (size_t)blockIdx.z * bz;
    C    += (size_t)blockIdx.z * cz;
    bias += (size_t)blockIdx.z * biasz;

    const __half* Ag = A + (size_t)row0 * lda;
    const __half* Bg = BT + (size_t)col0 * ldb;

    // copy mapping: 128 threads, A: 8 chunks/thread, B: 8 chunks/thread
    const int cr = tid >> 3;          // 0..15
    const int cc = tid & 7;           // logical 16B chunk

    // ldmatrix lane geometry
    const int lrA = wm + (lane & 15);
    const int lrB = wn + (lane & 15);
    const int hi  = lane >> 4;
    const int sxA = lrA & 7;
    const int sxB = lrB & 7;

    float acc[4][8][4];
#pragma unroll
    for (int mi = 0; mi < 4; mi++)
#pragma unroll
        for (int ni = 0; ni < 8; ni++)
#pragma unroll
            for (int j = 0; j < 4; j++) acc[mi][ni][j] = 0.f;

    const int nk = K / BKH;

    // prologue
#pragma unroll
    for (int s = 0; s < STAGES - 1; s++) {
        if (s < nk) {
            uint32_t as = sbase + s * STAGE_BYTES;
            uint32_t bs = as + A_BYTES;
            int k0 = s * BKH;
#pragma unroll
            for (int i = 0; i < 8; i++) {
                int r = cr + 16 * i, c = cc;
                cp16(as + r * 128 + ((c ^ (r & 7)) << 4),
                     Ag + (size_t)r * lda + k0 + c * 8);
                cp16(bs + r * 128 + ((c ^ (r & 7)) << 4),
                     Bg + (size_t)r * ldb + k0 + c * 8);
            }
        }
        asm volatile("cp.async.commit_group;\n");
    }

    for (int kt = 0; kt < nk; kt++) {
        asm volatile("cp.async.wait_group %0;\n" :: "n"(STAGES - 2));
        __syncthreads();

        // issue stage kt+STAGES-1
        {
            int kf = kt + STAGES - 1;
            if (kf < nk) {
                uint32_t as = sbase + (kf % STAGES) * STAGE_BYTES;
                uint32_t bs = as + A_BYTES;
                int k0 = kf * BKH;
#pragma unroll
                for (int i = 0; i < 8; i++) {
                    int r = cr + 16 * i, c = cc;
                    cp16(as + r * 128 + ((c ^ (r & 7)) << 4),
                         Ag + (size_t)r * lda + k0 + c * 8);
                    cp16(bs + r * 128 + ((c ^ (r & 7)) << 4),
                         Bg + (size_t)r * ldb + k0 + c * 8);
                }
            }
            asm volatile("cp.async.commit_group;\n");
        }

        const uint32_t abase = sbase + (kt % STAGES) * STAGE_BYTES + lrA * 128;
        const uint32_t bbase = sbase + (kt % STAGES) * STAGE_BYTES + A_BYTES + lrB * 128;

        uint32_t af[2][4][4], bf[2][4][4];
        {
            uint32_t chA = (uint32_t)((hi ^ sxA) << 4);
            uint32_t chB = (uint32_t)((hi ^ sxB) << 4);
#pragma unroll
            for (int mi = 0; mi < 4; mi++) ldsm4(af[0][mi], abase + mi * 2048 + chA);
#pragma unroll
            for (int p = 0; p < 4; p++) ldsm4(bf[0][p], bbase + p * 2048 + chB);
        }
#pragma unroll
        for (int s = 0; s < 4; s++) {
            int cur = s & 1, nxt = cur ^ 1;
            if (s < 3) {
                uint32_t chA = (uint32_t)(((2 * (s + 1) + hi) ^ sxA) << 4);
                uint32_t chB = (uint32_t)(((2 * (s + 1) + hi) ^ sxB) << 4);
#pragma unroll
                for (int mi = 0; mi < 4; mi++) ldsm4(af[nxt][mi], abase + mi * 2048 + chA);
#pragma unroll
                for (int p = 0; p < 4; p++) ldsm4(bf[nxt][p], bbase + p * 2048 + chB);
            }
#pragma unroll
            for (int mi = 0; mi < 4; mi++)
#pragma unroll
                for (int p = 0; p < 4; p++) {
                    mma_f16(acc[mi][2 * p],     af[cur][mi], bf[cur][p][0], bf[cur][p][2]);
                    mma_f16(acc[mi][2 * p + 1], af[cur][mi], bf[cur][p][1], bf[cur][p][3]);
                }
        }
        __syncthreads();
    }

    // epilogue
#pragma unroll
    for (int mi = 0; mi < 4; mi++) {
#pragma unroll
        for (int ni = 0; ni < 8; ni++) {
            int c = col0 + wn + ni * 8 + tig * 2;
            float2 bv = *(const float2*)(bias + c);
#pragma unroll
            for (int h = 0; h < 2; h++) {
                int r = row0 + wm + mi * 16 + gID + h * 8;
                float v0 = acc[mi][ni][h * 2 + 0] + bv.x;
                float v1 = acc[mi][ni][h * 2 + 1] + bv.y;
                if (EPI == 1) {
                    float2 rv = *(const float2*)(res + (size_t)r * ldc + c);
                    v0 += rv.x;
                    v1 += rv.y;
                    *(float2*)((float*)C + (size_t)r * ldc + c) = make_float2(v0, v1);
                } else if (EPI == 2) {
                    __half2 o = __floats2half2_rn(gelu_exact(v0), gelu_exact(v1));
                    *(__half2*)((__half*)C + (size_t)r * ldc + c) = o;
                } else {
                    __half2 o = __floats2half2_rn(v0, v1);
                    *(__half2*)((__half*)C + (size_t)r * ldc + c) = o;
                }
            }
        }
    }
}

// ---------------------------------------------------------------- launch
extern "C" void kernel_launch(void* const* d_in, const int* in_sizes, int n_in,
                              void* d_out, int out_size)
{
    const float* x     = (const float*)d_in[0];
    const float* W_qkv = (const float*)d_in[1];
    const float* b_qkv = (const float*)d_in[2];
    const float* W_out = (const float*)d_in[3];
    const float* b_out = (const float*)d_in[4];
    const float* ln1_g = (const float*)d_in[5];
    const float* ln1_b = (const float*)d_in[6];
    const float* ln2_g = (const float*)d_in[7];
    const float* ln2_b = (const float*)d_in[8];
    const float* W1    = (const float*)d_in[9];
    const float* b1    = (const float*)d_in[10];
    const float* W2    = (const float*)d_in[11];
    const float* b2    = (const float*)d_in[12];
    float* out = (float*)d_out;

    __half *s1, *s2, *w;
    float *xr;
    cudaGetSymbolAddress((void**)&s1, g_s1);
    cudaGetSymbolAddress((void**)&s2, g_s2);
    cudaGetSymbolAddress((void**)&xr, g_xr);
    cudaGetSymbolAddress((void**)&w,  g_w);

    cudaFuncSetAttribute((const void*)hgemm_kernel<0, __half>,
                         cudaFuncAttributeMaxDynamicSharedMemorySize, SMEMG_BYTES);
    cudaFuncSetAttribute((const void*)hgemm_kernel<1, float>,
                         cudaFuncAttributeMaxDynamicSharedMemorySize, SMEMG_BYTES);
    cudaFuncSetAttribute((const void*)hgemm_kernel<2, __half>,
                         cudaFuncAttributeMaxDynamicSharedMemorySize, SMEMG_BYTES);

    // 0) transpose + fp16-round all weights: W[K,N] -> WT[N,K]
    transpose_h_kernel<<<dim3(768 / 32, 256 / 32, 3), dim3(32, 8)>>>(W_qkv, w + WOFF_QKV, 256, 768);
    transpose_h_kernel<<<dim3(256 / 32, 256 / 32, 1), dim3(32, 8)>>>(W_out, w + WOFF_OUT, 256, 256);
    transpose_h_kernel<<<dim3(3072 / 32, 768 / 32, 1), dim3(32, 8)>>>(W1, w + WOFF_W1, 768, 3072);
    transpose_h_kernel<<<dim3(768 / 32, 3072 / 32, 1), dim3(32, 8)>>>(W2, w + WOFF_W2, 3072, 768);

    // 1) LN1: x -> h (s2, half)
    ln_kernel<<<T_TOK / 8, 256>>>(x, ln1_g, ln1_b, s2);

    // 2) QKV (all 3 channels, gridDim.z=3): [32768,256] @ [256,768] -> s1[T,2304]
    hgemm_kernel<0, __half><<<dim3(6, 256, 3), 128, SMEMG_BYTES>>>(
        KFD,
        s2, H_DIM, (size_t)KFD,
        w + WOFF_QKV, KFD, (size_t)768 * 256,
        s1, 2304, (size_t)768,
        b_qkv, (size_t)768,
        nullptr);

    // 3) attention: qkv(s1) -> ctx(s2) [T*3, 256] half
    attn_kernel<<<(T_TOK * KFD) / 256, 256>>>(s1, s2);

    // 4) out-proj + residual: [98304,256] @ [256,256] + x -> xr (fp32)
    hgemm_kernel<1, float><<<dim3(2, 768, 1), 128, SMEMG_BYTES>>>(
        KFD, s2, KFD, 0, w + WOFF_OUT, KFD, 0, xr, KFD, 0, b_out, 0, x);

    // 5) LN2: xr -> y (s2, half)
    ln_kernel<<<T_TOK / 8, 256>>>(xr, ln2_g, ln2_b, s2);

    // 6) MLP fc1 + GELU: [32768,768] @ [768,3072] -> act (s1, half)
    hgemm_kernel<2, __half><<<dim3(24, 256, 1), 128, SMEMG_BYTES>>>(
        H_DIM, s2, H_DIM, 0, w + WOFF_W1, H_DIM, 0, s1, M_MLP, 0, b1, 0, nullptr);

    // 7) MLP fc2 + residual: [32768,3072] @ [3072,768] + xr -> out (fp32)
    hgemm_kernel<1, float><<<dim3(6, 256, 1), 128, SMEMG_BYTES>>>(
        M_MLP, s1, M_MLP, 0, w + WOFF_W2, M_MLP, 0, out, H_DIM, 0, b2, 0, xr);
}